// round 14
// baseline (speedup 1.0000x reference)
#include <cuda_runtime.h>

#define H 512
#define W 512
#define NPTS 12
#define NMAPS 16          // B(8) * 2 groups
#define TSAT 21.0f        // d >= TSAT -> tanh(2*sqrt(d)) == 1.0f exactly in fp32
#define PCOL4 13
#define PROWS 47
#define PUNITS (PROWS * PCOL4)     // 611
#define NPATCH (NMAPS * NPTS)      // 192 patch blocks
#define NFILL  2048                // fill blocks (256 thr x 2 float4 each)

__device__ unsigned g_fill_done = 0;   // released by each fill block
__device__ unsigned g_patch_done = 0;  // for end-of-launch reset

// tanh(2*sqrt(d)) = 1 - 2/(exp(4*sqrt(d)) + 1); only called with d < TSAT.
__device__ __forceinline__ float fast_out(float d) {
    float s, t, r;
    asm("sqrt.approx.f32 %0, %1;" : "=f"(s) : "f"(d));
    float e = 5.770780163555852f * s;          // 4*log2(e)*sqrt(d)
    asm("ex2.approx.f32 %0, %1;" : "=f"(t) : "f"(e));
    float tp1 = t + 1.0f;
    asm("rcp.approx.f32 %0, %1;" : "=f"(r) : "f"(tp1));
    return fmaf(-2.0f, r, 1.0f);
}

// ONE launch. Blocks [0, 192): patch (precompute -> spin -> store).
// Blocks [192, 2240): fill (pure stores -> release).
__global__ __launch_bounds__(256) void distmaps_fused(
    const float4* __restrict__ coords4,   // (8,24,3) viewed as float4[144]
    float* __restrict__ out)              // (8, 2, 512, 512)
{
    const int bid = blockIdx.x;
    const int tid = threadIdx.x;

    if (bid >= NPATCH) {
        // ---------------- fill block: pure stores, then release ----------------
        const unsigned fb = bid - NPATCH;
        const float4 one = make_float4(1.0f, 1.0f, 1.0f, 1.0f);
        float4* o4 = (float4*)out;
        const unsigned idx = fb * 512u + tid;
        o4[idx]       = one;
        o4[idx + 256] = one;
        __threadfence();            // make stores visible before the release
        __syncthreads();
        if (tid == 0) atomicAdd(&g_fill_done, 1u);
        return;
    }

    // ---------------- patch block: overlap compute with fill ----------------
    const int m = bid / NPTS;       // map
    const int p = bid % NPTS;       // point

    __shared__ float sc[36];        // this map's 12 x (y, x, z)
    if (tid < 9) ((float4*)sc)[tid] = __ldg(coords4 + m * 9 + tid);
    __syncthreads();

    const float yp = sc[p * 3 + 0];
    const float xp = sc[p * 3 + 1];
    const bool validp = fmaxf(yp, xp) >= 0.0f;

    // Precompute up to 3 float4 units into registers (happens DURING fill).
    float4 vals[3];
    int    radr[3];
    int nunit = 0;
    if (validp) {
        const int iy = (int)floorf(yp);
        const int ix = (int)floorf(xp);
        const int r0 = iy - 23;
        const int cb = (ix - 23) & ~3;
#pragma unroll
        for (int k = 0; k < 3; k++) {
            const int u = tid + k * 256;
            if (u >= PUNITS) break;
            const int r = r0 + u / PCOL4;
            const int c = cb + (u % PCOL4) * 4;
            if (r < 0 || r >= H || c < 0 || c > W - 4) continue;

            const float rf  = (float)r;
            const float cs0 = (float)c * 0.2f;
            const float cs1 = (float)(c + 1) * 0.2f;
            const float cs2 = (float)(c + 2) * 0.2f;
            const float cs3 = (float)(c + 3) * 0.2f;

            float m0 = 1.0e6f, m1 = 1.0e6f, m2 = 1.0e6f, m3 = 1.0e6f;
#pragma unroll
            for (int j = 0; j < NPTS; j++) {
                float y = sc[j * 3 + 0];
                float x = sc[j * 3 + 1];
                float bse = (fmaxf(y, x) < 0.0f) ? 1000000.0f : 0.0f;
                float t = (rf - y) * 0.2f;
                float a = fmaf(t, t, bse);
                float nx = -x * 0.2f;
                float d0 = cs0 + nx, d1 = cs1 + nx, d2 = cs2 + nx, d3 = cs3 + nx;
                m0 = fminf(m0, fmaf(d0, d0, a));
                m1 = fminf(m1, fmaf(d1, d1, a));
                m2 = fminf(m2, fmaf(d2, d2, a));
                m3 = fminf(m3, fmaf(d3, d3, a));
            }
            float4 v;
            v.x = (m0 < TSAT) ? fast_out(m0) : 1.0f;
            v.y = (m1 < TSAT) ? fast_out(m1) : 1.0f;
            v.z = (m2 < TSAT) ? fast_out(m2) : 1.0f;
            v.w = (m3 < TSAT) ? fast_out(m3) : 1.0f;
            vals[nunit] = v;
            radr[nunit] = r * W + c;
            nunit++;
        }
    }

    // Wait for all fill blocks (acquire), then overwrite with patch values.
    if (tid == 0) {
        volatile unsigned* vc = (volatile unsigned*)&g_fill_done;
        while (*vc < NFILL) __nanosleep(64);
    }
    __syncthreads();
    __threadfence();                // acquire: fill stores now visible/ordered

    float* obase = out + (size_t)m * H * W;
    for (int i = 0; i < nunit; i++)
        *(float4*)(obase + radr[i]) = vals[i];

    // End-of-launch reset so the graph replay starts from a clean state.
    __threadfence();
    __syncthreads();
    if (tid == 0) {
        unsigned old = atomicAdd(&g_patch_done, 1u);
        if (old == NPATCH - 1) {    // last patch block: everyone is done
            g_fill_done = 0;
            __threadfence();
            g_patch_done = 0;
        }
    }
}

extern "C" void kernel_launch(void* const* d_in, const int* in_sizes, int n_in,
                              void* d_out, int out_size)
{
    const float* coords = nullptr;
    for (int i = 0; i < n_in; i++) {
        if (in_sizes[i] == 8 * 24 * 3) { coords = (const float*)d_in[i]; break; }
    }
    if (!coords) coords = (const float*)d_in[n_in - 1];

    float* out = (float*)d_out;

    distmaps_fused<<<NPATCH + NFILL, 256>>>((const float4*)coords, out);
}

// round 15
// speedup vs baseline: 1.1667x; 1.1667x over previous
#include <cuda_runtime.h>

#define H 512
#define W 512
#define NPTS 12
#define NMAPS 16          // B(8) * 2 groups
#define TSAT 21.0f        // d >= TSAT -> tanh(2*sqrt(d)) == 1.0f exactly in fp32
#define PCOL4 13
#define PROWS 47
#define PUNITS (PROWS * PCOL4)          // 611 float4 units per patch
#define NPATCH (NMAPS * NPTS)           // 192 patches
#define TOTAL_E (NPATCH * PUNITS)       // 117312 scratch entries
#define NFILL 2048
#define NPK ((TOTAL_E + 255) / 256)     // 459 patch-apply blocks

// Scratch: precomputed patch values + target addresses (-1 = skip).
__device__ float4 g_vals[TOTAL_E];
__device__ int    g_addrs[TOTAL_E];

// tanh(2*sqrt(d)) = 1 - 2/(exp(4*sqrt(d)) + 1); only called with d < TSAT.
__device__ __forceinline__ float fast_out(float d) {
    float s, t, r;
    asm("sqrt.approx.f32 %0, %1;" : "=f"(s) : "f"(d));
    float e = 5.770780163555852f * s;          // 4*log2(e)*sqrt(d)
    asm("ex2.approx.f32 %0, %1;" : "=f"(t) : "f"(e));
    float tp1 = t + 1.0f;
    asm("rcp.approx.f32 %0, %1;" : "=f"(r) : "f"(tp1));
    return fmaf(-2.0f, r, 1.0f);
}

// ---- Kernel 1: fill + (blocks 0..191) patch precompute into scratch.
// The precompute rides in the latency shadow of the store-bound fill.
__global__ __launch_bounds__(256) void fill_kernel(
    float4* __restrict__ out, const float4* __restrict__ coords4)
{
    const int bid = blockIdx.x;
    const int tid = threadIdx.x;

    // Fill stores first: every block, 2 float4.
    const float4 one = make_float4(1.0f, 1.0f, 1.0f, 1.0f);
    const unsigned idx = bid * 512u + tid;
    out[idx]       = one;
    out[idx + 256] = one;

    if (bid >= NPATCH) return;

    // ---- patch precompute (overlapped with other blocks' stores) ----
    const int m = bid / NPTS;
    const int p = bid % NPTS;

    __shared__ float sc[36];
    if (tid < 9) ((float4*)sc)[tid] = __ldg(coords4 + m * 9 + tid);
    __syncthreads();

    const float yp = sc[p * 3 + 0];
    const float xp = sc[p * 3 + 1];
    const bool validp = fmaxf(yp, xp) >= 0.0f;
    const int iy = (int)floorf(yp);
    const int ix = (int)floorf(xp);
    const int r0 = iy - 23;
    const int cb = (ix - 23) & ~3;

    const int ebase = bid * PUNITS;
#pragma unroll
    for (int k = 0; k < 3; k++) {
        const int u = tid + k * 256;
        if (u >= PUNITS) break;

        int   addr = -1;
        float4 v = make_float4(1.0f, 1.0f, 1.0f, 1.0f);

        const int r = r0 + u / PCOL4;
        const int c = cb + (u % PCOL4) * 4;
        if (validp && r >= 0 && r < H && c >= 0 && c <= W - 4) {
            const float rf  = (float)r;
            const float cs0 = (float)c * 0.2f;
            const float cs1 = (float)(c + 1) * 0.2f;
            const float cs2 = (float)(c + 2) * 0.2f;
            const float cs3 = (float)(c + 3) * 0.2f;

            float m0 = 1.0e6f, m1 = 1.0e6f, m2 = 1.0e6f, m3 = 1.0e6f;
#pragma unroll
            for (int j = 0; j < NPTS; j++) {
                float y = sc[j * 3 + 0];
                float x = sc[j * 3 + 1];
                float bse = (fmaxf(y, x) < 0.0f) ? 1000000.0f : 0.0f;
                float t = (rf - y) * 0.2f;
                float a = fmaf(t, t, bse);
                float nx = -x * 0.2f;
                float d0 = cs0 + nx, d1 = cs1 + nx, d2 = cs2 + nx, d3 = cs3 + nx;
                m0 = fminf(m0, fmaf(d0, d0, a));
                m1 = fminf(m1, fmaf(d1, d1, a));
                m2 = fminf(m2, fmaf(d2, d2, a));
                m3 = fminf(m3, fmaf(d3, d3, a));
            }
            v.x = (m0 < TSAT) ? fast_out(m0) : 1.0f;
            v.y = (m1 < TSAT) ? fast_out(m1) : 1.0f;
            v.z = (m2 < TSAT) ? fast_out(m2) : 1.0f;
            v.w = (m3 < TSAT) ? fast_out(m3) : 1.0f;
            addr = (m * H + r) * W + c;
        }

        g_vals[ebase + u]  = v;
        g_addrs[ebase + u] = addr;
    }
}

// ---- Kernel 2: pure gather/scatter. No math, no smem, no sync.
// One scratch entry per thread; everything L2-hot from kernel 1.
__global__ __launch_bounds__(256) void apply_kernel(float* __restrict__ out)
{
    const int g = blockIdx.x * 256 + threadIdx.x;
    if (g >= TOTAL_E) return;
    const int addr = g_addrs[g];
    if (addr >= 0) {
        float4 v = g_vals[g];
        *(float4*)(out + addr) = v;
    }
}

extern "C" void kernel_launch(void* const* d_in, const int* in_sizes, int n_in,
                              void* d_out, int out_size)
{
    const float* coords = nullptr;
    for (int i = 0; i < n_in; i++) {
        if (in_sizes[i] == 8 * 24 * 3) { coords = (const float*)d_in[i]; break; }
    }
    if (!coords) coords = (const float*)d_in[n_in - 1];

    float* out = (float*)d_out;

    fill_kernel<<<NFILL, 256>>>((float4*)out, (const float4*)coords);
    apply_kernel<<<NPK, 256>>>(out);
}

// round 16
// speedup vs baseline: 1.1805x; 1.0118x over previous
#include <cuda_runtime.h>
#include <cuda_device_runtime_api.h>

#define H 512
#define W 512
#define NPTS 12
#define NMAPS 16          // B(8) * 2 groups
#define TSAT 21.0f        // d >= TSAT -> tanh(2*sqrt(d)) == 1.0f exactly in fp32
#define PCOL4 13
#define PROWS 47
#define PUNITS (PROWS * PCOL4)     // 611 float4 units per patch
#define NPATCH (NMAPS * NPTS)      // 192 patch blocks
#define NFILL  2048

// tanh(2*sqrt(d)) = 1 - 2/(exp(4*sqrt(d)) + 1); only called with d < TSAT.
__device__ __forceinline__ float fast_out(float d) {
    float s, t, r;
    asm("sqrt.approx.f32 %0, %1;" : "=f"(s) : "f"(d));
    float e = 5.770780163555852f * s;          // 4*log2(e)*sqrt(d)
    asm("ex2.approx.f32 %0, %1;" : "=f"(t) : "f"(e));
    float tp1 = t + 1.0f;
    asm("rcp.approx.f32 %0, %1;" : "=f"(r) : "f"(tp1));
    return fmaf(-2.0f, r, 1.0f);
}

// ---- Kernel 1: pure fill. 2048 blocks x 256 threads, 2 float4/thread.
// Each block triggers the dependent (patch) launch right after its stores.
__global__ __launch_bounds__(256) void fill_kernel(float4* __restrict__ out)
{
    const float4 one = make_float4(1.0f, 1.0f, 1.0f, 1.0f);
    const unsigned idx = blockIdx.x * 512u + threadIdx.x;
    out[idx]       = one;
    out[idx + 256] = one;
    cudaTriggerProgrammaticLaunchCompletion();
}

// ---- Kernel 2 (PDL secondary): starts WHILE fill runs.
// Pre-dependency phase (overlapped): coords load + full compute into registers.
// Then cudaGridDependencySynchronize() -> fill's stores visible -> patch stores.
__global__ __launch_bounds__(256) void patch_kernel(
    const float4* __restrict__ coords4,   // (8,24,3) viewed as float4[144]
    float* __restrict__ out)              // (8, 2, 512, 512)
{
    const int bid = blockIdx.x;           // 0..191 = (map, point)
    const int tid = threadIdx.x;
    const int m = bid / NPTS;
    const int p = bid % NPTS;

    __shared__ float sc[36];              // this map's 12 x (y, x, z)
    if (tid < 9) ((float4*)sc)[tid] = __ldg(coords4 + m * 9 + tid);
    __syncthreads();

    const float yp = sc[p * 3 + 0];
    const float xp = sc[p * 3 + 1];
    const bool validp = fmaxf(yp, xp) >= 0.0f;

    // -------- overlapped compute: up to 3 float4 units into registers --------
    float4 vals[3];
    int    radr[3];
    int nunit = 0;
    if (validp) {
        const int iy = (int)floorf(yp);
        const int ix = (int)floorf(xp);
        const int r0 = iy - 23;
        const int cb = (ix - 23) & ~3;
#pragma unroll
        for (int k = 0; k < 3; k++) {
            const int u = tid + k * 256;
            if (u >= PUNITS) break;
            const int r = r0 + u / PCOL4;
            const int c = cb + (u % PCOL4) * 4;
            if (r < 0 || r >= H || c < 0 || c > W - 4) continue;

            const float rf  = (float)r;
            const float cs0 = (float)c * 0.2f;
            const float cs1 = (float)(c + 1) * 0.2f;
            const float cs2 = (float)(c + 2) * 0.2f;
            const float cs3 = (float)(c + 3) * 0.2f;

            float m0 = 1.0e6f, m1 = 1.0e6f, m2 = 1.0e6f, m3 = 1.0e6f;
#pragma unroll
            for (int j = 0; j < NPTS; j++) {
                float y = sc[j * 3 + 0];
                float x = sc[j * 3 + 1];
                float bse = (fmaxf(y, x) < 0.0f) ? 1000000.0f : 0.0f;
                float t = (rf - y) * 0.2f;
                float a = fmaf(t, t, bse);
                float nx = -x * 0.2f;
                float d0 = cs0 + nx, d1 = cs1 + nx, d2 = cs2 + nx, d3 = cs3 + nx;
                m0 = fminf(m0, fmaf(d0, d0, a));
                m1 = fminf(m1, fmaf(d1, d1, a));
                m2 = fminf(m2, fmaf(d2, d2, a));
                m3 = fminf(m3, fmaf(d3, d3, a));
            }
            float4 v;
            v.x = (m0 < TSAT) ? fast_out(m0) : 1.0f;
            v.y = (m1 < TSAT) ? fast_out(m1) : 1.0f;
            v.z = (m2 < TSAT) ? fast_out(m2) : 1.0f;
            v.w = (m3 < TSAT) ? fast_out(m3) : 1.0f;
            vals[nunit] = v;
            radr[nunit] = (m * H + r) * W + c;
            nunit++;
        }
    }

    // -------- dependency point: wait for fill grid's stores --------
    cudaGridDependencySynchronize();

    for (int i = 0; i < nunit; i++)
        *(float4*)(out + radr[i]) = vals[i];
}

extern "C" void kernel_launch(void* const* d_in, const int* in_sizes, int n_in,
                              void* d_out, int out_size)
{
    const float* coords = nullptr;
    for (int i = 0; i < n_in; i++) {
        if (in_sizes[i] == 8 * 24 * 3) { coords = (const float*)d_in[i]; break; }
    }
    if (!coords) coords = (const float*)d_in[n_in - 1];

    float* out = (float*)d_out;

    // Primary: fill.
    fill_kernel<<<NFILL, 256>>>((float4*)out);

    // Secondary: patch, launched with programmatic stream serialization so it
    // overlaps the fill and only serializes at cudaGridDependencySynchronize().
    cudaLaunchConfig_t cfg = {};
    cfg.gridDim  = dim3(NPATCH, 1, 1);
    cfg.blockDim = dim3(256, 1, 1);
    cfg.dynamicSmemBytes = 0;
    cfg.stream = 0;
    cudaLaunchAttribute attrs[1];
    attrs[0].id = cudaLaunchAttributeProgrammaticStreamSerialization;
    attrs[0].val.programmaticStreamSerializationAllowed = 1;
    cfg.attrs = attrs;
    cfg.numAttrs = 1;

    cudaError_t err = cudaLaunchKernelEx(&cfg, patch_kernel,
                                         (const float4*)coords, out);
    if (err != cudaSuccess) {
        // Fallback: plain serialized launch (correctness preserved).
        patch_kernel<<<NPATCH, 256>>>((const float4*)coords, out);
    }
}

// round 17
// speedup vs baseline: 1.5000x; 1.2707x over previous
#include <cuda_runtime.h>

#define H 512
#define W 512
#define NPTS 12
#define NMAPS 16          // B(8) * 2 groups
#define TSAT 21.0f        // d >= TSAT -> tanh(2*sqrt(d)) == 1.0f exactly in fp32
#define PCOL4 13
#define PROWS 47
#define NPATCH_BLK (NMAPS * NPTS * 2)   // 384 patch blocks (2 per patch)
#define NFILL_BLK 2048                   // fill blocks: 512 float4 each

// tanh(2*sqrt(d)) = 1 - 2/(exp(4*sqrt(d)) + 1); only called with d < TSAT.
__device__ __forceinline__ float fast_out(float d) {
    float s, t, r;
    asm("sqrt.approx.f32 %0, %1;" : "=f"(s) : "f"(d));
    float e = 5.770780163555852f * s;          // 4*log2(e)*sqrt(d)
    asm("ex2.approx.f32 %0, %1;" : "=f"(t) : "f"(e));
    float tp1 = t + 1.0f;
    asm("rcp.approx.f32 %0, %1;" : "=f"(r) : "f"(tp1));
    return fmaf(-2.0f, r, 1.0f);
}

// ONE kernel, one node.
//  bid <  384 : patch block — writes EVERY float4 in its half-bbox (incl. 1.0s).
//  bid >= 384 : fill block — pure-fill stores, skipping exactly the float4s
//               any patch block writes. Warp-local mask: no smem, no barriers.
__global__ __launch_bounds__(256, 6) void distmaps_onenode(
    const float* __restrict__ coords,   // (8, 24, 3)
    float* __restrict__ out)            // (8, 2, 512, 512)
{
    const int bid = blockIdx.x;
    const int tid = threadIdx.x;

    if (bid >= NPATCH_BLK) {
        // ================= FILL BLOCK =================
        const int f  = bid - NPATCH_BLK;        // 0..2047
        const int m  = f >> 7;                  // 128 blocks per map
        const int r0 = (f & 127) * 4;           // 4 rows per block
        const int w    = tid >> 5;              // warp 0..7
        const int lane = tid & 31;
        const int rA = r0 + (w >> 2);           // warp's two rows
        const int rB = rA + 2;
        const int w0 = (w & 3) * 32;            // warp's first float4 col

        // Warp-local coverage words for rows rA / rB over cols [w0, w0+31].
        unsigned bA = 0, bB = 0;
        if (lane < NPTS) {
            const float* q = coords + (m * NPTS + lane) * 3;
            float y = __ldg(q);
            float x = __ldg(q + 1);
            if (fmaxf(y, x) >= 0.0f) {
                const int iy = (int)floorf(y);
                const int ix = (int)floorf(x);
                const int fb = ((ix - 23) & ~3) >> 2;     // first f4 col
                int l = max(fb - w0, 0);
                int h = min(fb + 12 - w0, 31);
                if (h >= l) {
                    unsigned bits =
                        ((h == 31) ? 0xFFFFFFFFu : ((1u << (h + 1)) - 1u))
                        & ~((1u << l) - 1u);
                    const int rlo = iy - 23;
                    if ((unsigned)(rA - rlo) < (unsigned)PROWS) bA = bits;
                    if ((unsigned)(rB - rlo) < (unsigned)PROWS) bB = bits;
                }
            }
        }
        bA = __reduce_or_sync(0xffffffffu, bA);
        bB = __reduce_or_sync(0xffffffffu, bB);

        const int c4 = w0 + lane;
        const float4 one = make_float4(1.0f, 1.0f, 1.0f, 1.0f);
        float4* rowA = (float4*)(out + ((size_t)m * H + rA) * W);
        float4* rowB = (float4*)(out + ((size_t)m * H + rB) * W);
        if (!((bA >> lane) & 1u)) rowA[c4] = one;
        if (!((bB >> lane) & 1u)) rowB[c4] = one;
        return;
    }

    // ================= PATCH BLOCK =================
    const int pid  = bid >> 1;
    const int half = bid & 1;
    const int m = pid / NPTS;
    const int p = pid % NPTS;

    __shared__ float sc[36];            // this map's 12 x (y, x, z)
    if (tid < 9) ((float4*)sc)[tid] = __ldg((const float4*)coords + m * 9 + tid);
    __syncthreads();

    const float yp = sc[p * 3 + 0];
    const float xp = sc[p * 3 + 1];
    if (fmaxf(yp, xp) < 0.0f) return;   // invalid anchor: nothing to write
                                        // (fill doesn't skip for invalid pts)
    const int iy = (int)floorf(yp);
    const int ix = (int)floorf(xp);
    const int rbeg  = iy - 23 + half * 24;
    const int nrows = half ? (PROWS - 24) : 24;
    const int cb    = (ix - 23) & ~3;
    const int units = nrows * PCOL4;    // <= 312, so <= 2 per thread

    for (int u = tid; u < units; u += 256) {
        const int r = rbeg + u / PCOL4;
        const int c = cb + (u % PCOL4) * 4;
        if (r < 0 || r >= H || c < 0 || c > W - 4) continue;

        const float rf  = (float)r;
        const float cs0 = (float)c * 0.2f;
        const float cs1 = (float)(c + 1) * 0.2f;
        const float cs2 = (float)(c + 2) * 0.2f;
        const float cs3 = (float)(c + 3) * 0.2f;

        float m0 = 1.0e6f, m1 = 1.0e6f, m2 = 1.0e6f, m3 = 1.0e6f;
#pragma unroll
        for (int j = 0; j < NPTS; j++) {
            float y = sc[j * 3 + 0];
            float x = sc[j * 3 + 1];
            float bse = (fmaxf(y, x) < 0.0f) ? 1000000.0f : 0.0f;
            float t = (rf - y) * 0.2f;
            float a = fmaf(t, t, bse);
            float nx = -x * 0.2f;
            float d0 = cs0 + nx, d1 = cs1 + nx, d2 = cs2 + nx, d3 = cs3 + nx;
            m0 = fminf(m0, fmaf(d0, d0, a));
            m1 = fminf(m1, fmaf(d1, d1, a));
            m2 = fminf(m2, fmaf(d2, d2, a));
            m3 = fminf(m3, fmaf(d3, d3, a));
        }

        float4 v;
        v.x = (m0 < TSAT) ? fast_out(m0) : 1.0f;
        v.y = (m1 < TSAT) ? fast_out(m1) : 1.0f;
        v.z = (m2 < TSAT) ? fast_out(m2) : 1.0f;
        v.w = (m3 < TSAT) ? fast_out(m3) : 1.0f;

        *(float4*)(out + ((size_t)m * H + r) * W + c) = v;
    }
}

extern "C" void kernel_launch(void* const* d_in, const int* in_sizes, int n_in,
                              void* d_out, int out_size)
{
    const float* coords = nullptr;
    for (int i = 0; i < n_in; i++) {
        if (in_sizes[i] == 8 * 24 * 3) { coords = (const float*)d_in[i]; break; }
    }
    if (!coords) coords = (const float*)d_in[n_in - 1];

    float* out = (float*)d_out;

    distmaps_onenode<<<NPATCH_BLK + NFILL_BLK, 256>>>(coords, out);
}